// round 4
// baseline (speedup 1.0000x reference)
#include <cuda_runtime.h>

#define Bd 8
#define Nd 2048
#define F_IN 256
#define F_OUT 64
#define ALPHA 0.2f

#define TI 64
#define TJ 64
#define PSTRIDE 68   // 64 + 4 pad, keeps float4 alignment, breaks bank patterns

// Scratch (allocation-free rule: __device__ globals)
__device__ float g_Wh[Bd * Nd * F_OUT];   // 4 MB
__device__ float g_es[Bd * Nd];
__device__ float g_ed[Bd * Nd];

// ---------------------------------------------------------------------------
// Kernel 1: Wh = h @ W  (per-row), plus e_src = Wh.a1, e_dst = Wh.a2
// grid = B*N blocks, 64 threads each.
// Thread t: fgrp = t>>4 covers 64 f's, o4 = t&15 covers 4 outputs (float4 W).
// ---------------------------------------------------------------------------
__global__ __launch_bounds__(64) void wh_kernel(const float* __restrict__ h,
                                                const float* __restrict__ W,
                                                const float* __restrict__ a) {
    int row = blockIdx.x;  // 0 .. B*N-1
    __shared__ float hs[F_IN];
    __shared__ float4 part[64];

    int t = threadIdx.x;
    // stage h row (256 floats = 64 float4)
    ((float4*)hs)[t] = ((const float4*)(h + (size_t)row * F_IN))[t];
    __syncthreads();

    int fgrp = t >> 4;     // 0..3
    int o4   = t & 15;     // 0..15 -> outputs o4*4 .. +3
    const float4* W4 = (const float4*)W;   // [F_IN][16] of float4

    float4 acc = make_float4(0.f, 0.f, 0.f, 0.f);
    int fbase = fgrp * 64;
#pragma unroll 8
    for (int f = 0; f < 64; f++) {
        float hv = hs[fbase + f];
        float4 w = W4[(fbase + f) * 16 + o4];
        acc.x += hv * w.x; acc.y += hv * w.y;
        acc.z += hv * w.z; acc.w += hv * w.w;
    }
    part[t] = acc;
    __syncthreads();

    if (t < 16) {
        float4 p0 = part[t], p1 = part[t + 16], p2 = part[t + 32], p3 = part[t + 48];
        acc.x = p0.x + p1.x + p2.x + p3.x;
        acc.y = p0.y + p1.y + p2.y + p3.y;
        acc.z = p0.z + p1.z + p2.z + p3.z;
        acc.w = p0.w + p1.w + p2.w + p3.w;
        ((float4*)(g_Wh + (size_t)row * F_OUT))[t] = acc;

        const float4* a4 = (const float4*)a;   // a: 128 floats
        float4 a1 = a4[t];
        float4 a2 = a4[16 + t];
        float p = acc.x * a1.x + acc.y * a1.y + acc.z * a1.z + acc.w * a1.w;
        float q = acc.x * a2.x + acc.y * a2.y + acc.z * a2.z + acc.w * a2.w;
#pragma unroll
        for (int off = 8; off > 0; off >>= 1) {
            p += __shfl_xor_sync(0xFFFFu, p, off, 16);
            q += __shfl_xor_sync(0xFFFFu, q, off, 16);
        }
        if (t == 0) {
            g_es[row] = p;
            g_ed[row] = q;
        }
    }
}

// ---------------------------------------------------------------------------
// Kernel 2: fused attention + aggregation + ELU.
// grid = (N/TI, B), 256 threads.
// Per j-tile: P[i][j] = adj ? exp(lrelu(es_i + ed_j)) : 0  (no max-subtraction
// needed: scores bounded ~10, exp stays < 2e4; masked rows cannot occur).
// acc[TIxF_OUT] += P @ Wh_tile via 4x4 register tiling; rowsum tracked in smem.
// ---------------------------------------------------------------------------
__global__ __launch_bounds__(256) void gat_kernel(const int* __restrict__ adj,
                                                  float* __restrict__ out) {
    __shared__ float Ps[TI][PSTRIDE];
    __shared__ float Whs[TJ][PSTRIDE];
    __shared__ float es_s[TI];
    __shared__ float ed_s[TJ];
    __shared__ float rowsum[TI];

    int t  = threadIdx.x;
    int b  = blockIdx.y;
    int i0 = blockIdx.x * TI;

    if (t < TI) rowsum[t] = 0.f;
    if (t < 16) ((float4*)es_s)[t] = ((const float4*)(g_es + (size_t)b * Nd + i0))[t];
    __syncthreads();

    // P-generation mapping: row pi (0..63), j-quad jq (0..3) -> 16 j's each
    int pi = t >> 2;
    int jq = t & 3;
    float esi = es_s[pi];

    // GEMM mapping: 16x16 thread grid, 4x4 micro-tile
    int ty = t >> 4;       // rows ty*4 .. +3
    int tx = t & 15;       // cols tx*4 .. +3
    float acc[4][4] = {};

    const float* Whb    = g_Wh + (size_t)b * Nd * F_OUT;
    const float* edb    = g_ed + (size_t)b * Nd;
    const int*   adjrow = adj + (size_t)b * Nd * Nd + (size_t)(i0 + pi) * Nd;

    // load indices for Wh tile staging
    int lr = t >> 2;       // row within tile 0..63
    int lp = t & 3;        // 4 float4's per thread

    for (int j0 = 0; j0 < Nd; j0 += TJ) {
        __syncthreads();   // previous GEMM done reading Ps/Whs

        // stage Wh tile [TJ][F_OUT] and ed tile
        {
            const float4* src = (const float4*)(Whb + (size_t)(j0 + lr) * F_OUT);
            float4* dst = (float4*)(&Whs[lr][0]);
#pragma unroll
            for (int q = 0; q < 4; q++)
                dst[lp * 4 + q] = src[lp * 4 + q];
            if (t < 16)
                ((float4*)ed_s)[t] = ((const float4*)(edb + j0))[t];
        }
        __syncthreads();

        // compute P tile + partial row sums
        float psum = 0.f;
        const int4* arow = (const int4*)(adjrow + j0);
#pragma unroll
        for (int q = 0; q < 4; q++) {
            int4 av = arow[jq * 4 + q];
            int jb = jq * 16 + q * 4;
            float4 p;
            float e;
            e = esi + ed_s[jb + 0]; e = (e > 0.f) ? e : ALPHA * e; p.x = av.x ? __expf(e) : 0.f;
            e = esi + ed_s[jb + 1]; e = (e > 0.f) ? e : ALPHA * e; p.y = av.y ? __expf(e) : 0.f;
            e = esi + ed_s[jb + 2]; e = (e > 0.f) ? e : ALPHA * e; p.z = av.z ? __expf(e) : 0.f;
            e = esi + ed_s[jb + 3]; e = (e > 0.f) ? e : ALPHA * e; p.w = av.w ? __expf(e) : 0.f;
            psum += p.x + p.y + p.z + p.w;
            *(float4*)(&Ps[pi][jb]) = p;
        }
        psum += __shfl_xor_sync(0xFFFFFFFFu, psum, 1);
        psum += __shfl_xor_sync(0xFFFFFFFFu, psum, 2);
        if (jq == 0) rowsum[pi] += psum;   // single writer per pi
        __syncthreads();

        // acc += P @ Whs   (64x64x64)
#pragma unroll 4
        for (int k = 0; k < TJ; k++) {
            float a0 = Ps[ty * 4 + 0][k];
            float a1 = Ps[ty * 4 + 1][k];
            float a2 = Ps[ty * 4 + 2][k];
            float a3 = Ps[ty * 4 + 3][k];
            float4 bv = *(const float4*)(&Whs[k][tx * 4]);
            acc[0][0] += a0 * bv.x; acc[0][1] += a0 * bv.y; acc[0][2] += a0 * bv.z; acc[0][3] += a0 * bv.w;
            acc[1][0] += a1 * bv.x; acc[1][1] += a1 * bv.y; acc[1][2] += a1 * bv.z; acc[1][3] += a1 * bv.w;
            acc[2][0] += a2 * bv.x; acc[2][1] += a2 * bv.y; acc[2][2] += a2 * bv.z; acc[2][3] += a2 * bv.w;
            acc[3][0] += a3 * bv.x; acc[3][1] += a3 * bv.y; acc[3][2] += a3 * bv.z; acc[3][3] += a3 * bv.w;
        }
    }
    __syncthreads();

    // epilogue: divide by rowsum, ELU, store
#pragma unroll
    for (int m = 0; m < 4; m++) {
        int row = ty * 4 + m;
        float inv = 1.0f / rowsum[row];
        float4 o;
        float v;
        v = acc[m][0] * inv; o.x = (v > 0.f) ? v : expm1f(v);
        v = acc[m][1] * inv; o.y = (v > 0.f) ? v : expm1f(v);
        v = acc[m][2] * inv; o.z = (v > 0.f) ? v : expm1f(v);
        v = acc[m][3] * inv; o.w = (v > 0.f) ? v : expm1f(v);
        *(float4*)(out + ((size_t)b * Nd + i0 + row) * F_OUT + tx * 4) = o;
    }
}

// ---------------------------------------------------------------------------
extern "C" void kernel_launch(void* const* d_in, const int* in_sizes, int n_in,
                              void* d_out, int out_size) {
    const float* h   = (const float*)d_in[0];   // (8,2048,256) f32
    const int*   adj = (const int*)d_in[1];     // (8,2048,2048) i32
    const float* W   = (const float*)d_in[2];   // (256,64) f32
    const float* a   = (const float*)d_in[3];   // (128,1) f32
    float* out = (float*)d_out;                 // (8,2048,64) f32

    wh_kernel<<<Bd * Nd, 64>>>(h, W, a);
    dim3 grid(Nd / TI, Bd);
    gat_kernel<<<grid, 256>>>(adj, out);
}

// round 8
// speedup vs baseline: 2.0963x; 2.0963x over previous
#include <cuda_runtime.h>

#define Bd 8
#define Nd 2048
#define F_IN 256
#define F_OUT 64
#define ALPHA 0.2f

#define TI 64
#define TJ 64
#define SPLIT 4
#define JPB (Nd / SPLIT)   // 512 j's per block
#define PST 68             // smem row stride (floats), 16B-aligned

typedef unsigned long long ull;

// ---- packed f32x2 helpers (sm_103a FFMA2: 2x fp32 FMA throughput) ----
__device__ __forceinline__ void fma2(ull& d, ull a, ull b) {
    asm("fma.rn.f32x2 %0, %1, %2, %0;" : "+l"(d) : "l"(a), "l"(b));
}
__device__ __forceinline__ ull pack2(float x) {
    ull r; asm("mov.b64 %0, {%1, %1};" : "=l"(r) : "f"(x)); return r;
}
__device__ __forceinline__ void unpack2(float& lo, float& hi, ull v) {
    asm("mov.b64 {%0, %1}, %2;" : "=f"(lo), "=f"(hi) : "l"(v));
}

// ---- scratch (__device__ globals; allocation-free rule) ----
__device__ __align__(16) float g_Wh[Bd * Nd * F_OUT];            // 4 MB
__device__ __align__(16) float g_es[Bd * Nd];
__device__ __align__(16) float g_ed[Bd * Nd];
__device__ __align__(16) float g_pacc[SPLIT * Bd * Nd * F_OUT];  // 16 MB partials
__device__ __align__(16) float g_prs[SPLIT * Bd * Nd];           // partial rowsums

// ---------------------------------------------------------------------------
// Kernel 1: Wh = h @ W, e_src = Wh.a1, e_dst = Wh.a2.
// 256 threads = 16 rows x 16 col-quads. Each thread owns 4 outputs for one
// row: full dot over F_IN, no cross-thread accumulation needed for Wh.
// ---------------------------------------------------------------------------
__global__ __launch_bounds__(256) void wh_kernel(const float* __restrict__ h,
                                                 const float* __restrict__ W,
                                                 const float* __restrict__ a) {
    __shared__ float  hs[16][68];      // 16 rows x 64-f chunk (padded)
    __shared__ float4 Ws[64][16];      // 64-f chunk x 16 col-quads (16 KB)

    int t    = threadIdx.x;
    int row0 = blockIdx.x * 16;
    int r    = t >> 4;                 // local row 0..15
    int o4   = t & 15;                 // col quad 0..15

    const float4* h4 = (const float4*)h;
    const float4* W4 = (const float4*)W;   // [F_IN][16]

    ull acc0 = 0ull, acc1 = 0ull;      // 4 outputs as 2 f32x2 pairs

    for (int c = 0; c < 4; c++) {      // F_IN in chunks of 64
        __syncthreads();
        // stage h chunk: each thread one float4
        *(float4*)&hs[r][o4 * 4] = h4[(size_t)(row0 + r) * 64 + c * 16 + o4];
        // stage W chunk: 1024 float4, 4 per thread, linear = coalesced
#pragma unroll
        for (int q = 0; q < 4; q++) {
            int idx = t * 4 + q;
            int f = idx >> 4, col = idx & 15;
            Ws[f][col] = W4[(size_t)(c * 64 + f) * 16 + col];
        }
        __syncthreads();
#pragma unroll 16
        for (int f = 0; f < 64; f++) {
            ull hp = pack2(hs[r][f]);
            ulonglong2 wv = *(const ulonglong2*)&Ws[f][o4];
            fma2(acc0, hp, wv.x);
            fma2(acc1, hp, wv.y);
        }
    }

    float4 wh;
    unpack2(wh.x, wh.y, acc0);
    unpack2(wh.z, wh.w, acc1);
    int row = row0 + r;
    *(float4*)(g_Wh + (size_t)row * F_OUT + o4 * 4) = wh;

    // attention logits: per-thread partial dot with a1/a2, reduce over 16 lanes
    const float4* a4 = (const float4*)a;
    float4 a1 = a4[o4];
    float4 a2 = a4[16 + o4];
    float p = wh.x * a1.x + wh.y * a1.y + wh.z * a1.z + wh.w * a1.w;
    float q = wh.x * a2.x + wh.y * a2.y + wh.z * a2.z + wh.w * a2.w;
#pragma unroll
    for (int off = 8; off > 0; off >>= 1) {
        p += __shfl_xor_sync(0xFFFFFFFFu, p, off, 16);
        q += __shfl_xor_sync(0xFFFFFFFFu, q, off, 16);
    }
    if (o4 == 0) {
        g_es[row] = p;
        g_ed[row] = q;
    }
}

// ---------------------------------------------------------------------------
// Kernel 2: fused attention + aggregation, split-K over j (4-way).
// grid (N/TI, B, SPLIT), 256 threads. P tile is stored TRANSPOSED in smem
// (PsT[j][i ^ (j & 0x3C)]: XOR swizzle keeps float4 loads aligned, stores
// <=2-way conflicted) so both GEMM operands are LDS.128, and the 4x4 micro
// tile accumulates via FFMA2 (8 packed FMAs per k instead of 16 scalar).
// Softmax needs no max-subtraction: scores bounded ~10 (es,ed ~ N(0,1.8^2)).
// ---------------------------------------------------------------------------
__global__ __launch_bounds__(256, 4) void gat_kernel(const int* __restrict__ adj) {
    __shared__ float PsT[TJ][PST];
    __shared__ float Whs[TJ][PST];
    __shared__ float es_s[TI];
    __shared__ float ed_s[TJ];
    __shared__ float rowsum[TI];

    int t     = threadIdx.x;
    int b     = blockIdx.y;
    int i0    = blockIdx.x * TI;
    int split = blockIdx.z;
    int jbase = split * JPB;

    if (t < TI) rowsum[t] = 0.f;
    if (t < 16) ((float4*)es_s)[t] = ((const float4*)(g_es + (size_t)b * Nd + i0))[t];
    __syncthreads();

    // P-generation mapping: row pi (0..63), j-quad jq (0..3)
    int pi = t >> 2;
    int jq = t & 3;
    float esi = es_s[pi];

    // GEMM mapping: 16x16 threads, 4x4 micro-tile, f32x2 accumulators
    int ty = t >> 4;
    int tx = t & 15;
    ull acc[4][2] = {};

    const float* Whb    = g_Wh + (size_t)b * Nd * F_OUT;
    const float* edb    = g_ed + (size_t)b * Nd;
    const int*   adjrow = adj + (size_t)b * Nd * Nd + (size_t)(i0 + pi) * Nd;

    int lr = t >> 2;       // Wh staging: row in tile
    int lp = t & 3;        // 4 float4's per thread

    for (int j0 = jbase; j0 < jbase + JPB; j0 += TJ) {
        __syncthreads();   // previous GEMM done with PsT/Whs/ed_s

        {   // stage Wh tile + ed tile
            const float4* src = (const float4*)(Whb + (size_t)(j0 + lr) * F_OUT);
            float4* dst = (float4*)&Whs[lr][0];
#pragma unroll
            for (int q = 0; q < 4; q++) dst[lp * 4 + q] = src[lp * 4 + q];
            if (t < 16) ((float4*)ed_s)[t] = ((const float4*)(edb + j0))[t];
        }
        __syncthreads();

        // P tile (transposed+swizzled) + partial row sums
        float psum = 0.f;
        const int4* arow = (const int4*)(adjrow + j0);
#pragma unroll
        for (int q = 0; q < 4; q++) {
            int4 av = arow[jq * 4 + q];
            int jb  = jq * 16 + q * 4;       // j & 0x3C for this quad
            int col = pi ^ jb;               // swizzled column
            float e, p0, p1, p2, p3;
            e = esi + ed_s[jb + 0]; e = (e > 0.f) ? e : ALPHA * e; p0 = av.x ? __expf(e) : 0.f;
            e = esi + ed_s[jb + 1]; e = (e > 0.f) ? e : ALPHA * e; p1 = av.y ? __expf(e) : 0.f;
            e = esi + ed_s[jb + 2]; e = (e > 0.f) ? e : ALPHA * e; p2 = av.z ? __expf(e) : 0.f;
            e = esi + ed_s[jb + 3]; e = (e > 0.f) ? e : ALPHA * e; p3 = av.w ? __expf(e) : 0.f;
            psum += p0 + p1 + p2 + p3;
            PsT[jb + 0][col] = p0;
            PsT[jb + 1][col] = p1;
            PsT[jb + 2][col] = p2;
            PsT[jb + 3][col] = p3;
        }
        psum += __shfl_xor_sync(0xFFFFFFFFu, psum, 1);
        psum += __shfl_xor_sync(0xFFFFFFFFu, psum, 2);
        if (jq == 0) rowsum[pi] += psum;
        __syncthreads();

        // acc += P @ Whs  (64x64x64), all-LDS.128 + FFMA2
#pragma unroll 16
        for (int k = 0; k < TJ; k++) {
            float4 av = *(const float4*)&PsT[k][(ty * 4) ^ (k & 0x3C)];
            ulonglong2 bv = *(const ulonglong2*)&Whs[k][tx * 4];
            ull a0 = pack2(av.x), a1 = pack2(av.y), a2 = pack2(av.z), a3 = pack2(av.w);
            fma2(acc[0][0], a0, bv.x); fma2(acc[0][1], a0, bv.y);
            fma2(acc[1][0], a1, bv.x); fma2(acc[1][1], a1, bv.y);
            fma2(acc[2][0], a2, bv.x); fma2(acc[2][1], a2, bv.y);
            fma2(acc[3][0], a3, bv.x); fma2(acc[3][1], a3, bv.y);
        }
    }
    __syncthreads();

    // write unnormalized partials + partial rowsums
    float* pacc = g_pacc + (((size_t)split * Bd + b) * Nd + i0) * F_OUT;
#pragma unroll
    for (int m = 0; m < 4; m++) {
        float4 o;
        unpack2(o.x, o.y, acc[m][0]);
        unpack2(o.z, o.w, acc[m][1]);
        *(float4*)(pacc + (size_t)(ty * 4 + m) * F_OUT + tx * 4) = o;
    }
    if (t < TI) g_prs[((size_t)split * Bd + b) * Nd + i0 + t] = rowsum[t];
}

// ---------------------------------------------------------------------------
// Kernel 3: sum the 4 split partials, normalize, ELU, store.
// ---------------------------------------------------------------------------
__global__ __launch_bounds__(256) void reduce_kernel(float* __restrict__ out) {
    int tid = blockIdx.x * 256 + threadIdx.x;   // 0 .. B*N*16-1
    int row = tid >> 4;                          // b*N + i
    int c4  = tid & 15;

    float4 s = make_float4(0.f, 0.f, 0.f, 0.f);
    float rs = 0.f;
#pragma unroll
    for (int sp = 0; sp < SPLIT; sp++) {
        float4 v = *(const float4*)(g_pacc + ((size_t)sp * Bd * Nd + row) * F_OUT + c4 * 4);
        s.x += v.x; s.y += v.y; s.z += v.z; s.w += v.w;
        rs += g_prs[(size_t)sp * Bd * Nd + row];
    }
    float inv = 1.0f / rs;
    float4 o; float v;
    v = s.x * inv; o.x = (v > 0.f) ? v : expm1f(v);
    v = s.y * inv; o.y = (v > 0.f) ? v : expm1f(v);
    v = s.z * inv; o.z = (v > 0.f) ? v : expm1f(v);
    v = s.w * inv; o.w = (v > 0.f) ? v : expm1f(v);
    *(float4*)(out + (size_t)row * F_OUT + c4 * 4) = o;
}

// ---------------------------------------------------------------------------
extern "C" void kernel_launch(void* const* d_in, const int* in_sizes, int n_in,
                              void* d_out, int out_size) {
    const float* h   = (const float*)d_in[0];   // (8,2048,256) f32
    const int*   adj = (const int*)d_in[1];     // (8,2048,2048) i32
    const float* W   = (const float*)d_in[2];   // (256,64) f32
    const float* a   = (const float*)d_in[3];   // (128,1) f32
    float* out = (float*)d_out;                 // (8,2048,64) f32

    wh_kernel<<<Bd * Nd / 16, 256>>>(h, W, a);
    dim3 grid(Nd / TI, Bd, SPLIT);
    gat_kernel<<<grid, 256>>>(adj);
    reduce_kernel<<<Bd * Nd * 16 / 256, 256>>>(out);
}